// round 1
// baseline (speedup 1.0000x reference)
#include <cuda_runtime.h>
#include <cuda_bf16.h>

#define NN   50000
#define NRL  20
#define DEMB 64
#define DHID 128

// Static scratch (no allocations allowed). agg is reused across both layers.
__device__ float g_agg[(long)NN * NRL * DHID];          // 512 MB
__device__ float g_cnt[NN * NRL];                       // 4 MB
__device__ float g_inv[NN * NRL];                       // 4 MB
__device__ float g_h1[(long)NN * DHID];                 // 25.6 MB
__device__ float g_h2[(long)NN * DHID];                 // 25.6 MB
__device__ float g_B1[(NRL * DEMB + DEMB) * DHID];      // 1344 x 128
__device__ float g_B2[(NRL * DHID + DHID) * DHID];      // 2688 x 128

__global__ void zero_kernel(float4* p, long n4) {
    long i = (long)blockIdx.x * blockDim.x + threadIdx.x;
    long stride = (long)gridDim.x * blockDim.x;
    float4 z = make_float4(0.f, 0.f, 0.f, 0.f);
    for (; i < n4; i += stride) p[i] = z;
}

__global__ void count_kernel(const int* __restrict__ dst, const int* __restrict__ et,
                             int E, float* __restrict__ cnt) {
    int i = blockIdx.x * blockDim.x + threadIdx.x;
    if (i < E) atomicAdd(&cnt[dst[i] * NRL + et[i]], 1.0f);
}

__global__ void inv_kernel(const float* __restrict__ cnt, float* __restrict__ inv, int n) {
    int i = blockIdx.x * blockDim.x + threadIdx.x;
    if (i < n) inv[i] = 1.0f / fmaxf(cnt[i], 1.0f);
}

// Each edge handled by DIN/4 threads; one float4 vector-red per thread.
template <int DIN>
__global__ void scatter_kernel(const int* __restrict__ src, const int* __restrict__ dst,
                               const int* __restrict__ et, const float* __restrict__ X,
                               int E, float* __restrict__ agg) {
    const int L = DIN / 4;
    long t = (long)blockIdx.x * blockDim.x + threadIdx.x;
    int e = (int)(t / L);
    int sub = (int)(t % L);
    if (e >= E) return;
    int s = src[e], d = dst[e], r = et[e];
    float4 v = reinterpret_cast<const float4*>(X + (long)s * DIN)[sub];
    float* p = agg + ((long)d * NRL + r) * DIN + sub * 4;
    asm volatile("red.global.add.v4.f32 [%0], {%1,%2,%3,%4};"
                 :: "l"(p), "f"(v.x), "f"(v.y), "f"(v.z), "f"(v.w) : "memory");
}

// Concatenate W [R*din,128] and root [din,128] into one B matrix.
__global__ void prep_kernel(const float* __restrict__ W, const float* __restrict__ root,
                            float* __restrict__ B, int wElems, int rootElems) {
    int total = wElems + rootElems;
    for (int i = blockIdx.x * blockDim.x + threadIdx.x; i < total;
         i += gridDim.x * blockDim.x) {
        B[i] = (i < wElems) ? W[i] : root[i - wElems];
    }
}

// C[NN,128] = A[NN, R*DIN + DIN] @ B[.,128] + bias, optional ReLU.
// A is virtual: k < KA -> agg[n*KA+k] * inv[n*NRL + k/DIN]; else X[n*DIN + k-KA].
template <int DIN>
__global__ void __launch_bounds__(256, 2)
gemm_kernel(const float* __restrict__ Aagg, const float* __restrict__ inv,
            const float* __restrict__ X, const float* __restrict__ B,
            const float* __restrict__ bias, float* __restrict__ C, int relu) {
    const int KA = NRL * DIN;
    const int KT = KA + DIN;
    __shared__ float As[8][132];
    __shared__ float Bs[8][132];

    int tid = threadIdx.x;
    int tx = tid & 15;        // output col group
    int ty = tid >> 4;        // output row group
    int bm = blockIdx.x * 128;

    int am = tid >> 1;        // A-load row (0..127)
    int ak = (tid & 1) * 4;   // A-load k offset (0 or 4)
    int bk = tid >> 5;        // B-load k row (0..7)
    int bn = (tid & 31) * 4;  // B-load col

    float acc[8][8];
#pragma unroll
    for (int i = 0; i < 8; i++)
#pragma unroll
        for (int j = 0; j < 8; j++) acc[i][j] = 0.f;

    for (int k0 = 0; k0 < KT; k0 += 8) {
        // Load A tile 128x8 (one float4 per thread)
        int n = bm + am;
        float4 av = make_float4(0.f, 0.f, 0.f, 0.f);
        if (n < NN) {
            int k = k0 + ak;
            if (k < KA) {
                float sc = inv[n * NRL + k / DIN];
                av = *reinterpret_cast<const float4*>(Aagg + (long)n * KA + k);
                av.x *= sc; av.y *= sc; av.z *= sc; av.w *= sc;
            } else {
                av = *reinterpret_cast<const float4*>(X + (long)n * DIN + (k - KA));
            }
        }
        As[ak + 0][am] = av.x;
        As[ak + 1][am] = av.y;
        As[ak + 2][am] = av.z;
        As[ak + 3][am] = av.w;

        // Load B tile 8x128 (one float4 per thread)
        *reinterpret_cast<float4*>(&Bs[bk][bn]) =
            *reinterpret_cast<const float4*>(B + (long)(k0 + bk) * DHID + bn);

        __syncthreads();

#pragma unroll
        for (int kk = 0; kk < 8; kk++) {
            float a[8], b[8];
#pragma unroll
            for (int i = 0; i < 8; i++) a[i] = As[kk][ty * 8 + i];
#pragma unroll
            for (int j = 0; j < 8; j++) b[j] = Bs[kk][tx * 8 + j];
#pragma unroll
            for (int i = 0; i < 8; i++)
#pragma unroll
                for (int j = 0; j < 8; j++) acc[i][j] += a[i] * b[j];
        }
        __syncthreads();
    }

#pragma unroll
    for (int i = 0; i < 8; i++) {
        int n = bm + ty * 8 + i;
        if (n >= NN) continue;
#pragma unroll
        for (int j = 0; j < 8; j++) {
            int col = tx * 8 + j;
            float v = acc[i][j] + bias[col];
            if (relu) v = fmaxf(v, 0.f);
            C[(long)n * DHID + col] = v;
        }
    }
}

__global__ void decoder_kernel(const int* __restrict__ head, const int* __restrict__ tail,
                               const int* __restrict__ rel, const float* __restrict__ h,
                               const float* __restrict__ rel_emb, float* __restrict__ out,
                               int Bn) {
    int warp = (blockIdx.x * blockDim.x + threadIdx.x) >> 5;
    int lane = threadIdx.x & 31;
    if (warp >= Bn) return;
    const float4* hp = reinterpret_cast<const float4*>(h + (long)head[warp] * DHID);
    const float4* tp = reinterpret_cast<const float4*>(h + (long)tail[warp] * DHID);
    const float4* rp = reinterpret_cast<const float4*>(rel_emb + (long)rel[warp] * DHID);
    float4 a = hp[lane], b = tp[lane], c = rp[lane];
    float s = a.x * b.x * c.x + a.y * b.y * c.y + a.z * b.z * c.z + a.w * b.w * c.w;
#pragma unroll
    for (int o = 16; o; o >>= 1) s += __shfl_xor_sync(0xffffffffu, s, o);
    if (lane == 0) out[warp] = s;
}

extern "C" void kernel_launch(void* const* d_in, const int* in_sizes, int n_in,
                              void* d_out, int out_size) {
    const int*   edge_index = (const int*)d_in[0];
    const int*   edge_type  = (const int*)d_in[1];
    const int*   head       = (const int*)d_in[2];
    const int*   tail       = (const int*)d_in[3];
    const int*   rel        = (const int*)d_in[4];
    const float* node_emb   = (const float*)d_in[5];
    const float* W1         = (const float*)d_in[6];
    const float* root1      = (const float*)d_in[7];
    const float* b1         = (const float*)d_in[8];
    const float* W2         = (const float*)d_in[9];
    const float* root2      = (const float*)d_in[10];
    const float* b2         = (const float*)d_in[11];
    const float* rel_emb    = (const float*)d_in[12];

    int E = in_sizes[0] / 2;
    const int* src = edge_index;
    const int* dst = edge_index + E;

    float *agg, *cnt, *inv, *h1, *h2, *B1, *B2;
    cudaGetSymbolAddress((void**)&agg, g_agg);
    cudaGetSymbolAddress((void**)&cnt, g_cnt);
    cudaGetSymbolAddress((void**)&inv, g_inv);
    cudaGetSymbolAddress((void**)&h1, g_h1);
    cudaGetSymbolAddress((void**)&h2, g_h2);
    cudaGetSymbolAddress((void**)&B1, g_B1);
    cudaGetSymbolAddress((void**)&B2, g_B2);

    const int T = 256;

    // ---- shared prep: counts / inverse counts (graph is identical both layers)
    zero_kernel<<<1024, T>>>((float4*)cnt, (long)NN * NRL / 4);
    count_kernel<<<(E + T - 1) / T, T>>>(dst, edge_type, E, cnt);
    inv_kernel<<<(NN * NRL + T - 1) / T, T>>>(cnt, inv, NN * NRL);

    // ---- layer 1
    zero_kernel<<<4096, T>>>((float4*)agg, (long)NN * NRL * DEMB / 4);
    {
        long threads = (long)E * (DEMB / 4);
        scatter_kernel<DEMB><<<(unsigned)((threads + T - 1) / T), T>>>(
            src, dst, edge_type, node_emb, E, agg);
    }
    prep_kernel<<<512, T>>>(W1, root1, B1, NRL * DEMB * DHID, DEMB * DHID);
    gemm_kernel<DEMB><<<(NN + 127) / 128, T>>>(agg, inv, node_emb, B1, b1, h1, 1);

    // ---- layer 2
    zero_kernel<<<8192, T>>>((float4*)agg, (long)NN * NRL * DHID / 4);
    {
        long threads = (long)E * (DHID / 4);
        scatter_kernel<DHID><<<(unsigned)((threads + T - 1) / T), T>>>(
            src, dst, edge_type, h1, E, agg);
    }
    prep_kernel<<<512, T>>>(W2, root2, B2, NRL * DHID * DHID, DHID * DHID);
    gemm_kernel<DHID><<<(NN + 127) / 128, T>>>(agg, inv, h1, B2, b2, h2, 0);

    // ---- DistMult decoder
    int Bn = in_sizes[2];
    decoder_kernel<<<(Bn * 32 + T - 1) / T, T>>>(head, tail, rel, h2, rel_emb,
                                                 (float*)d_out, Bn);
}